// round 1
// baseline (speedup 1.0000x reference)
#include <cuda_runtime.h>
#include <cstdint>

#define LATDIM 128

// ---------------------------------------------------------------------------
// Zero-fill output (d_out is poisoned to 0xAA by the harness).
// ---------------------------------------------------------------------------
__global__ void gcn_zero_kernel(float4* __restrict__ out, int n4) {
    int i = blockIdx.x * blockDim.x + threadIdx.x;
    int stride = gridDim.x * blockDim.x;
    float4 z = make_float4(0.f, 0.f, 0.f, 0.f);
    for (; i < n4; i += stride) out[i] = z;
}

// ---------------------------------------------------------------------------
// Warp-per-edge scatter-add:
//   out[rows[e]] += vals[e] * embeds[cols[e]]
// Lane l handles 4 floats (columns 4l..4l+3) -> one float4 gather + one
// red.global.add.v4.f32 (no-return vector reduction, sm_90+).
// ---------------------------------------------------------------------------
__global__ void __launch_bounds__(256) gcn_edge_kernel(
    const int*   __restrict__ rows,
    const int*   __restrict__ cols,
    const float* __restrict__ vals,
    const float* __restrict__ embeds,
    float*       __restrict__ out,
    int E)
{
    const int lane    = threadIdx.x & 31;
    const int warp    = (blockIdx.x * blockDim.x + threadIdx.x) >> 5;
    const int n_warps = (gridDim.x * blockDim.x) >> 5;
    const int col4    = lane * 4;

    for (int e = warp; e < E; e += n_warps) {
        const int   r = __ldg(rows + e);
        const int   c = __ldg(cols + e);
        const float v = __ldg(vals + e);

        const float4 x = *reinterpret_cast<const float4*>(
            embeds + (size_t)c * LATDIM + col4);

        float* dst = out + (size_t)r * LATDIM + col4;
        asm volatile(
            "red.global.add.v4.f32 [%0], {%1, %2, %3, %4};"
            :: "l"(dst), "f"(v * x.x), "f"(v * x.y), "f"(v * x.z), "f"(v * x.w)
            : "memory");
    }
}

// ---------------------------------------------------------------------------
// kernel_launch
// Inputs (metadata order):
//   d_in[0]: adj_indices int32 [2, E]  (rows = first E, cols = next E)
//   d_in[1]: adj_values  float32 [E]
//   d_in[2]: embeds      float32 [N, 128]
//   d_in[3]: batch_size  (unused)
// Output: float32 [N, 128]
// ---------------------------------------------------------------------------
extern "C" void kernel_launch(void* const* d_in, const int* in_sizes, int n_in,
                              void* d_out, int out_size)
{
    const int E = in_sizes[0] / 2;

    const int*   idx    = (const int*)  d_in[0];
    const float* vals   = (const float*)d_in[1];
    const float* embeds = (const float*)d_in[2];
    float*       out    = (float*)      d_out;

    const int* rows = idx;
    const int* cols = idx + E;

    // Zero the output.
    {
        int n4 = out_size / 4;
        int threads = 256;
        int blocks  = 148 * 16;
        gcn_zero_kernel<<<blocks, threads>>>((float4*)out, n4);
    }

    // Edge scatter-add.
    {
        int threads = 256;               // 8 warps/block
        int blocks  = 148 * 32;          // 4736 blocks -> ~38k warps
        gcn_edge_kernel<<<blocks, threads>>>(rows, cols, vals, embeds, out, E);
    }
}